// round 4
// baseline (speedup 1.0000x reference)
#include <cuda_runtime.h>
#include <cuda_bf16.h>
#include <cstdint>

// GroupQueryAttention: B=2, S=2048, HIDDEN=2048, H=32, HK=8, D=64
// Pipeline: sgemm(Q) sgemm(K) sgemm(V) -> flash attention -> sgemm(O)

#define BATCH 2
#define SEQ 2048
#define HIDDEN 2048
#define NH 32
#define NKV 8
#define HD 64
#define KVDIM 512
#define MTOT (BATCH * SEQ)   // 4096

// ---------------- scratch (static device globals; no allocation) -------------
__device__ float g_q[MTOT * HIDDEN];    // 32 MB
__device__ float g_k[MTOT * KVDIM];     // 8 MB
__device__ float g_v[MTOT * KVDIM];     // 8 MB
__device__ float g_attn[MTOT * HIDDEN]; // 32 MB

// ---------------- SGEMM: C[M,N] = A[M,K] @ W[N,K]^T + bias[N] ----------------
// Classic 128x128x8 block, 256 threads, 8x8 register tile per thread.
#define GBM 128
#define GBN 128
#define GBK 8
#define GTM 8
#define GTN 8

__global__ __launch_bounds__(256)
void sgemm_nt_bias(const float* __restrict__ A, const float* __restrict__ W,
                   const float* __restrict__ bias, float* __restrict__ C,
                   int M, int N, int K)
{
    __shared__ __align__(16) float As[GBK][GBM];
    __shared__ __align__(16) float Ws[GBK][GBN];

    const int tid = threadIdx.x;
    const int bx = blockIdx.x;   // N tile
    const int by = blockIdx.y;   // M tile
    const int tx = tid & 15;
    const int ty = tid >> 4;

    const float* Ab = A + (size_t)by * GBM * K;
    const float* Wb = W + (size_t)bx * GBN * K;

    float acc[GTM][GTN];
    #pragma unroll
    for (int i = 0; i < GTM; ++i)
        #pragma unroll
        for (int j = 0; j < GTN; ++j) acc[i][j] = 0.f;

    for (int k0 = 0; k0 < K; k0 += GBK) {
        #pragma unroll
        for (int l = 0; l < (GBM * GBK) / 256; ++l) {
            int idx = tid + l * 256;
            int r = idx / GBK, c = idx % GBK;
            As[c][r] = Ab[(size_t)r * K + k0 + c];
        }
        #pragma unroll
        for (int l = 0; l < (GBN * GBK) / 256; ++l) {
            int idx = tid + l * 256;
            int r = idx / GBK, c = idx % GBK;
            Ws[c][r] = Wb[(size_t)r * K + k0 + c];
        }
        __syncthreads();

        #pragma unroll
        for (int kk = 0; kk < GBK; ++kk) {
            float a[GTM], w[GTN];
            #pragma unroll
            for (int i = 0; i < GTM; ++i) a[i] = As[kk][ty * GTM + i];
            #pragma unroll
            for (int j = 0; j < GTN; ++j) w[j] = Ws[kk][tx * GTN + j];
            #pragma unroll
            for (int i = 0; i < GTM; ++i)
                #pragma unroll
                for (int j = 0; j < GTN; ++j)
                    acc[i][j] += a[i] * w[j];
        }
        __syncthreads();
    }

    #pragma unroll
    for (int i = 0; i < GTM; ++i) {
        int row = by * GBM + ty * GTM + i;
        #pragma unroll
        for (int j = 0; j < GTN; ++j) {
            int col = bx * GBN + tx * GTN + j;
            C[(size_t)row * N + col] = acc[i][j] + bias[col];
        }
    }
}

// ---------------- Flash attention -------------------------------------------
// Grid: (B*NH, SEQ/128). 128 threads; each thread owns one query row.
// K/V tiles of 64 keys staged in shared memory; online softmax in 8-key chunks
// so per-thread score array stays fully register-resident.
#define AT_BM 128
#define AT_BN 64
#define AT_CH 8
#define QSTRIDE 65   // padded to kill LDS bank conflicts on the q copy

__global__ __launch_bounds__(128)
void gqa_attention(const float* __restrict__ Q, const float* __restrict__ Kb,
                   const float* __restrict__ Vb, float* __restrict__ O)
{
    __shared__ __align__(16) float sm[AT_BM * QSTRIDE];  // 33280 B

    const int tid = threadIdx.x;
    const int bh = blockIdx.x;     // b*NH + h
    const int qt = blockIdx.y;
    const int b = bh / NH;
    const int h = bh % NH;
    const int kvh = h / (NH / NKV);

    const float* Qp = Q + (size_t)(b * SEQ) * HIDDEN + h * HD;
    const float* Kp = Kb + (size_t)(b * SEQ) * KVDIM + kvh * HD;
    const float* Vp = Vb + (size_t)(b * SEQ) * KVDIM + kvh * HD;

    // Stage this block's Q tile (coalesced), then copy own row to registers.
    #pragma unroll
    for (int l = 0; l < (AT_BM * HD) / 128; ++l) {
        int idx = tid + l * 128;
        int r = idx >> 6, d = idx & 63;
        sm[r * QSTRIDE + d] = Qp[(size_t)(qt * AT_BM + r) * HIDDEN + d];
    }
    __syncthreads();
    float q[HD];
    #pragma unroll
    for (int d = 0; d < HD; ++d) q[d] = sm[tid * QSTRIDE + d];
    __syncthreads();

    float acc[HD];
    #pragma unroll
    for (int d = 0; d < HD; ++d) acc[d] = 0.f;
    float mrun = -1e30f;
    float lsum = 0.f;
    const float scale = 0.125f;  // 1/sqrt(64)

    float* Ks = sm;               // 64*64 floats
    float* Vs = sm + AT_BN * HD;  // 64*64 floats (8192 <= 8320 total)

    for (int kt = 0; kt < SEQ; kt += AT_BN) {
        // coalesced K/V tile loads
        #pragma unroll
        for (int l = 0; l < (AT_BN * HD) / 128; ++l) {
            int idx = tid + l * 128;
            int r = idx >> 6, d = idx & 63;
            Ks[r * HD + d] = Kp[(size_t)(kt + r) * KVDIM + d];
            Vs[r * HD + d] = Vp[(size_t)(kt + r) * KVDIM + d];
        }
        __syncthreads();

        for (int jc = 0; jc < AT_BN; jc += AT_CH) {
            float sc[AT_CH];
            float tmax = mrun;
            #pragma unroll
            for (int j = 0; j < AT_CH; ++j) {
                float dot = 0.f;
                #pragma unroll
                for (int d = 0; d < HD; ++d)
                    dot += q[d] * Ks[(jc + j) * HD + d];
                sc[j] = dot * scale;
                tmax = fmaxf(tmax, sc[j]);
            }
            float corr = __expf(mrun - tmax);
            mrun = tmax;
            lsum *= corr;
            #pragma unroll
            for (int d = 0; d < HD; ++d) acc[d] *= corr;
            #pragma unroll
            for (int j = 0; j < AT_CH; ++j) {
                float p = __expf(sc[j] - tmax);
                lsum += p;
                #pragma unroll
                for (int d = 0; d < HD; ++d)
                    acc[d] += p * Vs[(jc + j) * HD + d];
            }
        }
        __syncthreads();
    }

    const float inv = 1.f / lsum;
    const size_t orow = (size_t)(b * SEQ + qt * AT_BM + tid) * HIDDEN + h * HD;
    #pragma unroll
    for (int d = 0; d < HD; ++d) O[orow + d] = acc[d] * inv;
}

// ---------------- launch ------------------------------------------------------
extern "C" void kernel_launch(void* const* d_in, const int* in_sizes, int n_in,
                              void* d_out, int out_size)
{
    const float* x  = (const float*)d_in[0];
    const float* wq = (const float*)d_in[1];
    const float* bq = (const float*)d_in[2];
    const float* wk = (const float*)d_in[3];
    const float* bk = (const float*)d_in[4];
    const float* wv = (const float*)d_in[5];
    const float* bv = (const float*)d_in[6];
    const float* wo = (const float*)d_in[7];
    const float* bo = (const float*)d_in[8];
    float* out = (float*)d_out;

    float *q, *k, *v, *attn;
    cudaGetSymbolAddress((void**)&q, g_q);
    cudaGetSymbolAddress((void**)&k, g_k);
    cudaGetSymbolAddress((void**)&v, g_v);
    cudaGetSymbolAddress((void**)&attn, g_attn);

    // Q/K/V projections
    sgemm_nt_bias<<<dim3(HIDDEN / GBN, MTOT / GBM), 256>>>(x, wq, bq, q, MTOT, HIDDEN, HIDDEN);
    sgemm_nt_bias<<<dim3(KVDIM / GBN,  MTOT / GBM), 256>>>(x, wk, bk, k, MTOT, KVDIM, HIDDEN);
    sgemm_nt_bias<<<dim3(KVDIM / GBN,  MTOT / GBM), 256>>>(x, wv, bv, v, MTOT, KVDIM, HIDDEN);

    // attention
    gqa_attention<<<dim3(BATCH * NH, SEQ / AT_BM), 128>>>(q, k, v, attn);

    // output projection
    sgemm_nt_bias<<<dim3(HIDDEN / GBN, MTOT / GBM), 256>>>(attn, wo, bo, out, MTOT, HIDDEN, HIDDEN);
}

// round 7
// speedup vs baseline: 1.6296x; 1.6296x over previous
#include <cuda_runtime.h>
#include <cuda_bf16.h>
#include <cstdint>

// GroupQueryAttention: B=2, S=2048, HIDDEN=2048, H=32, HK=8, D=64
// R6: GEMMs on tensor cores via arch-generic mma.sync (bf16 split, fp32-accurate).
// (tcgen05 is unavailable: harness compiles through compute_103 virtual arch.)

#define BATCH 2
#define SEQ 2048
#define HIDDEN 2048
#define NH 32
#define NKV 8
#define HD 64
#define KVDIM 512
#define MTOT (BATCH * SEQ)   // 4096

// ---------------- scratch (static device globals; no allocation) -------------
__device__ float g_q[MTOT * HIDDEN];
__device__ float g_k[MTOT * KVDIM];
__device__ float g_v[MTOT * KVDIM];
__device__ float g_attn[MTOT * HIDDEN];

// ======================= PTX helpers (arch-generic, sm_80+) ==================
__device__ __forceinline__ uint32_t smem_u32(const void* p) {
    uint32_t a;
    asm("{ .reg .u64 t; cvta.to.shared.u64 t, %1; cvt.u32.u64 %0, t; }"
        : "=r"(a) : "l"(p));
    return a;
}
__device__ __forceinline__ void ldm_x4(uint32_t* r, uint32_t addr) {
    asm volatile("ldmatrix.sync.aligned.m8n8.x4.shared.b16 {%0,%1,%2,%3}, [%4];"
                 : "=r"(r[0]), "=r"(r[1]), "=r"(r[2]), "=r"(r[3]) : "r"(addr));
}
__device__ __forceinline__ void mma16816(float* d, const uint32_t* a, const uint32_t* b) {
    asm volatile("mma.sync.aligned.m16n8k16.row.col.f32.bf16.bf16.f32 "
                 "{%0,%1,%2,%3}, {%4,%5,%6,%7}, {%8,%9}, {%0,%1,%2,%3};"
                 : "+f"(d[0]), "+f"(d[1]), "+f"(d[2]), "+f"(d[3])
                 : "r"(a[0]), "r"(a[1]), "r"(a[2]), "r"(a[3]), "r"(b[0]), "r"(b[1]));
}

// ============= split-bf16 tensor-core GEMM: C = A[M,K] @ W[N,K]^T + bias =====
#define BM 128
#define BN 128
#define BK 32
#define STR 40                      // padded bf16 row stride (80 B, conflict-free ldmatrix)
#define OFF_AHI 0
#define OFF_ALO (BM * STR)          // 5120 elems
#define OFF_BHI (2 * BM * STR)      // 10240
#define OFF_BLO (2 * BM * STR + BN * STR)  // 15360
#define STAGE_ELEMS (2 * BM * STR + 2 * BN * STR)  // 20480 bf16
#define GEMM_SMEM (2 * STAGE_ELEMS * 2)            // 81920 bytes

__device__ __forceinline__ void split_store4(__nv_bfloat16* hp, __nv_bfloat16* lp, float4 v) {
    __nv_bfloat16 h0 = __float2bfloat16(v.x), h1 = __float2bfloat16(v.y);
    __nv_bfloat16 h2 = __float2bfloat16(v.z), h3 = __float2bfloat16(v.w);
    __nv_bfloat16 l0 = __float2bfloat16(v.x - __bfloat162float(h0));
    __nv_bfloat16 l1 = __float2bfloat16(v.y - __bfloat162float(h1));
    __nv_bfloat16 l2 = __float2bfloat16(v.z - __bfloat162float(h2));
    __nv_bfloat16 l3 = __float2bfloat16(v.w - __bfloat162float(h3));
    __nv_bfloat162 p;
    p.x = h0; p.y = h1; *(__nv_bfloat162*)(hp)     = p;
    p.x = h2; p.y = h3; *(__nv_bfloat162*)(hp + 2) = p;
    p.x = l0; p.y = l1; *(__nv_bfloat162*)(lp)     = p;
    p.x = l2; p.y = l3; *(__nv_bfloat162*)(lp + 2) = p;
}

__global__ __launch_bounds__(256)
void mma_gemm_split(const float* __restrict__ A, const float* __restrict__ W,
                    const float* __restrict__ bias, float* __restrict__ C,
                    int M, int N, int K)
{
    extern __shared__ __align__(16) __nv_bfloat16 sm[];
    const int tid = threadIdx.x;
    const int lane = tid & 31, wid = tid >> 5;
    const int wm = wid & 3;      // 4 warps along M (32 rows each)
    const int wn = wid >> 2;     // 2 warps along N (64 cols each)
    const int bx = blockIdx.x, by = blockIdx.y;

    const float* Ab = A + (size_t)(by * BM) * K;
    const float* Wb = W + (size_t)(bx * BN) * K;

    float acc[2][8][4];
    #pragma unroll
    for (int i = 0; i < 2; ++i)
        #pragma unroll
        for (int j = 0; j < 8; ++j)
            #pragma unroll
            for (int t = 0; t < 4; ++t) acc[i][j][t] = 0.f;

    float4 ra[4], rb[4];   // register staging: 16 floats A + 16 floats B per iter

    const uint32_t sbase = smem_u32(sm);
    // per-lane ldmatrix byte offsets (within a tile, before k/frag offsets)
    const uint32_t aoff = (uint32_t)((wm * 32 + (lane & 15)) * STR) * 2 + (lane >> 4) * 16;
    const uint32_t boff = (uint32_t)((wn * 64 + (lane & 7) + ((lane >> 4) << 3)) * STR) * 2
                        + ((lane >> 3) & 1) * 16;

    const int nit = K / BK;

    // ---- prologue: stage chunk 0 ----
    {
        #pragma unroll
        for (int l = 0; l < 4; ++l) {
            int slot = tid + l * 256;
            int r = slot >> 3, q = slot & 7;
            ra[l] = *(const float4*)(Ab + (size_t)r * K + q * 4);
            rb[l] = *(const float4*)(Wb + (size_t)r * K + q * 4);
        }
        #pragma unroll
        for (int l = 0; l < 4; ++l) {
            int slot = tid + l * 256;
            int r = slot >> 3, q = slot & 7;
            int off = r * STR + q * 4;
            split_store4(sm + OFF_AHI + off, sm + OFF_ALO + off, ra[l]);
            split_store4(sm + OFF_BHI + off, sm + OFF_BLO + off, rb[l]);
        }
        __syncthreads();
    }

    for (int i = 0; i < nit; ++i) {
        // prefetch next chunk into registers
        if (i + 1 < nit) {
            const int k0 = (i + 1) * BK;
            #pragma unroll
            for (int l = 0; l < 4; ++l) {
                int slot = tid + l * 256;
                int r = slot >> 3, q = slot & 7;
                ra[l] = *(const float4*)(Ab + (size_t)r * K + k0 + q * 4);
                rb[l] = *(const float4*)(Wb + (size_t)r * K + k0 + q * 4);
            }
        }

        // ---- compute on stage i&1 ----
        {
            const uint32_t sa = sbase + (uint32_t)((i & 1) * STAGE_ELEMS) * 2;
            #pragma unroll
            for (int ks = 0; ks < 2; ++ks) {
                const uint32_t kb = ks * 32;   // 16 bf16 = 32 bytes
                uint32_t ah[2][4], al[2][4], bh[4][4], bl[4][4];
                #pragma unroll
                for (int mf = 0; mf < 2; ++mf) {
                    ldm_x4(ah[mf], sa + OFF_AHI * 2 + aoff + mf * (16 * STR * 2) + kb);
                    ldm_x4(al[mf], sa + OFF_ALO * 2 + aoff + mf * (16 * STR * 2) + kb);
                }
                #pragma unroll
                for (int nb = 0; nb < 4; ++nb) {
                    ldm_x4(bh[nb], sa + OFF_BHI * 2 + boff + nb * (16 * STR * 2) + kb);
                    ldm_x4(bl[nb], sa + OFF_BLO * 2 + boff + nb * (16 * STR * 2) + kb);
                }
                #pragma unroll
                for (int mf = 0; mf < 2; ++mf)
                    #pragma unroll
                    for (int nf = 0; nf < 8; ++nf) {
                        const uint32_t* bhp = &bh[nf >> 1][(nf & 1) * 2];
                        const uint32_t* blp = &bl[nf >> 1][(nf & 1) * 2];
                        mma16816(acc[mf][nf], ah[mf], bhp);  // hi*hi
                        mma16816(acc[mf][nf], ah[mf], blp);  // hi*lo
                        mma16816(acc[mf][nf], al[mf], bhp);  // lo*hi
                    }
            }
        }

        // stage next chunk into the other buffer
        if (i + 1 < nit) {
            __nv_bfloat16* base = sm + ((i + 1) & 1) * STAGE_ELEMS;
            #pragma unroll
            for (int l = 0; l < 4; ++l) {
                int slot = tid + l * 256;
                int r = slot >> 3, q = slot & 7;
                int off = r * STR + q * 4;
                split_store4(base + OFF_AHI + off, base + OFF_ALO + off, ra[l]);
                split_store4(base + OFF_BHI + off, base + OFF_BLO + off, rb[l]);
            }
        }
        __syncthreads();
    }

    // ---- epilogue: D frag -> C + bias ----
    const int row0 = by * BM + wm * 32 + (lane >> 2);
    const int col0 = bx * BN + wn * 64 + 2 * (lane & 3);
    #pragma unroll
    for (int mf = 0; mf < 2; ++mf) {
        #pragma unroll
        for (int nf = 0; nf < 8; ++nf) {
            const int r0 = row0 + mf * 16;
            const int c = col0 + nf * 8;
            const float b0 = bias[c], b1 = bias[c + 1];
            float2 v0 = make_float2(acc[mf][nf][0] + b0, acc[mf][nf][1] + b1);
            float2 v1 = make_float2(acc[mf][nf][2] + b0, acc[mf][nf][3] + b1);
            *(float2*)(C + (size_t)r0 * N + c) = v0;
            *(float2*)(C + (size_t)(r0 + 8) * N + c) = v1;
        }
    }
}

// ---------------- Flash attention (unchanged, verified) ----------------------
#define AT_BM 128
#define AT_BN 64
#define AT_CH 8
#define QSTRIDE 65

__global__ __launch_bounds__(128)
void gqa_attention(const float* __restrict__ Q, const float* __restrict__ Kb,
                   const float* __restrict__ Vb, float* __restrict__ O)
{
    __shared__ __align__(16) float sm[AT_BM * QSTRIDE];

    const int tid = threadIdx.x;
    const int bh = blockIdx.x;
    const int qt = blockIdx.y;
    const int b = bh / NH;
    const int h = bh % NH;
    const int kvh = h / (NH / NKV);

    const float* Qp = Q + (size_t)(b * SEQ) * HIDDEN + h * HD;
    const float* Kp = Kb + (size_t)(b * SEQ) * KVDIM + kvh * HD;
    const float* Vp = Vb + (size_t)(b * SEQ) * KVDIM + kvh * HD;

    #pragma unroll
    for (int l = 0; l < (AT_BM * HD) / 128; ++l) {
        int idx = tid + l * 128;
        int r = idx >> 6, d = idx & 63;
        sm[r * QSTRIDE + d] = Qp[(size_t)(qt * AT_BM + r) * HIDDEN + d];
    }
    __syncthreads();
    float q[HD];
    #pragma unroll
    for (int d = 0; d < HD; ++d) q[d] = sm[tid * QSTRIDE + d];
    __syncthreads();

    float acc[HD];
    #pragma unroll
    for (int d = 0; d < HD; ++d) acc[d] = 0.f;
    float mrun = -1e30f;
    float lsum = 0.f;
    const float scale = 0.125f;

    float* Ks = sm;
    float* Vs = sm + AT_BN * HD;

    for (int kt = 0; kt < SEQ; kt += AT_BN) {
        #pragma unroll
        for (int l = 0; l < (AT_BN * HD) / 128; ++l) {
            int idx = tid + l * 128;
            int r = idx >> 6, d = idx & 63;
            Ks[r * HD + d] = Kp[(size_t)(kt + r) * KVDIM + d];
            Vs[r * HD + d] = Vp[(size_t)(kt + r) * KVDIM + d];
        }
        __syncthreads();

        for (int jc = 0; jc < AT_BN; jc += AT_CH) {
            float sc[AT_CH];
            float tmax = mrun;
            #pragma unroll
            for (int j = 0; j < AT_CH; ++j) {
                float dot = 0.f;
                #pragma unroll
                for (int d = 0; d < HD; ++d)
                    dot += q[d] * Ks[(jc + j) * HD + d];
                sc[j] = dot * scale;
                tmax = fmaxf(tmax, sc[j]);
            }
            float corr = __expf(mrun - tmax);
            mrun = tmax;
            lsum *= corr;
            #pragma unroll
            for (int d = 0; d < HD; ++d) acc[d] *= corr;
            #pragma unroll
            for (int j = 0; j < AT_CH; ++j) {
                float p = __expf(sc[j] - tmax);
                lsum += p;
                #pragma unroll
                for (int d = 0; d < HD; ++d)
                    acc[d] += p * Vs[(jc + j) * HD + d];
            }
        }
        __syncthreads();
    }

    const float inv = 1.f / lsum;
    const size_t orow = (size_t)(b * SEQ + qt * AT_BM + tid) * HIDDEN + h * HD;
    #pragma unroll
    for (int d = 0; d < HD; ++d) O[orow + d] = acc[d] * inv;
}

// ---------------- launch ------------------------------------------------------
extern "C" void kernel_launch(void* const* d_in, const int* in_sizes, int n_in,
                              void* d_out, int out_size)
{
    const float* x  = (const float*)d_in[0];
    const float* wq = (const float*)d_in[1];
    const float* bq = (const float*)d_in[2];
    const float* wk = (const float*)d_in[3];
    const float* bk = (const float*)d_in[4];
    const float* wv = (const float*)d_in[5];
    const float* bv = (const float*)d_in[6];
    const float* wo = (const float*)d_in[7];
    const float* bo = (const float*)d_in[8];
    float* out = (float*)d_out;

    float *q, *k, *v, *attn;
    cudaGetSymbolAddress((void**)&q, g_q);
    cudaGetSymbolAddress((void**)&k, g_k);
    cudaGetSymbolAddress((void**)&v, g_v);
    cudaGetSymbolAddress((void**)&attn, g_attn);

    cudaFuncSetAttribute(mma_gemm_split,
                         cudaFuncAttributeMaxDynamicSharedMemorySize, GEMM_SMEM);

    // Q/K/V projections (tensor cores, split-bf16)
    mma_gemm_split<<<dim3(HIDDEN / BN, MTOT / BM), 256, GEMM_SMEM>>>(x, wq, bq, q, MTOT, HIDDEN, HIDDEN);
    mma_gemm_split<<<dim3(KVDIM / BN,  MTOT / BM), 256, GEMM_SMEM>>>(x, wk, bk, k, MTOT, KVDIM, HIDDEN);
    mma_gemm_split<<<dim3(KVDIM / BN,  MTOT / BM), 256, GEMM_SMEM>>>(x, wv, bv, v, MTOT, KVDIM, HIDDEN);

    // attention (fp32 flash, unchanged)
    gqa_attention<<<dim3(BATCH * NH, SEQ / AT_BM), 128>>>(q, k, v, attn);

    // output projection
    mma_gemm_split<<<dim3(HIDDEN / BN, MTOT / BM), 256, GEMM_SMEM>>>(attn, wo, bo, out, MTOT, HIDDEN, HIDDEN);
}

// round 8
// speedup vs baseline: 4.5164x; 2.7715x over previous
#include <cuda_runtime.h>
#include <cuda_bf16.h>
#include <cstdint>

// GroupQueryAttention: B=2, S=2048, HIDDEN=2048, H=32, HK=8, D=64
// R7: attention moved to tensor cores too (split-bf16 QK^T and PV, fp32 softmax).

#define BATCH 2
#define SEQ 2048
#define HIDDEN 2048
#define NH 32
#define NKV 8
#define HD 64
#define KVDIM 512
#define MTOT (BATCH * SEQ)   // 4096

// ---------------- scratch (static device globals; no allocation) -------------
__device__ __nv_bfloat16 g_qhi[MTOT * HIDDEN], g_qlo[MTOT * HIDDEN];
__device__ __nv_bfloat16 g_khi[MTOT * KVDIM], g_klo[MTOT * KVDIM];
__device__ __nv_bfloat16 g_vhi[MTOT * KVDIM], g_vlo[MTOT * KVDIM];
__device__ float g_attn[MTOT * HIDDEN];

// ======================= PTX helpers (arch-generic, sm_80+) ==================
__device__ __forceinline__ uint32_t smem_u32(const void* p) {
    uint32_t a;
    asm("{ .reg .u64 t; cvta.to.shared.u64 t, %1; cvt.u32.u64 %0, t; }"
        : "=r"(a) : "l"(p));
    return a;
}
__device__ __forceinline__ void ldm_x4(uint32_t* r, uint32_t addr) {
    asm volatile("ldmatrix.sync.aligned.m8n8.x4.shared.b16 {%0,%1,%2,%3}, [%4];"
                 : "=r"(r[0]), "=r"(r[1]), "=r"(r[2]), "=r"(r[3]) : "r"(addr));
}
__device__ __forceinline__ void ldm_x4_t(uint32_t* r, uint32_t addr) {
    asm volatile("ldmatrix.sync.aligned.m8n8.x4.trans.shared.b16 {%0,%1,%2,%3}, [%4];"
                 : "=r"(r[0]), "=r"(r[1]), "=r"(r[2]), "=r"(r[3]) : "r"(addr));
}
__device__ __forceinline__ void mma16816(float* d, const uint32_t* a, const uint32_t* b) {
    asm volatile("mma.sync.aligned.m16n8k16.row.col.f32.bf16.bf16.f32 "
                 "{%0,%1,%2,%3}, {%4,%5,%6,%7}, {%8,%9}, {%0,%1,%2,%3};"
                 : "+f"(d[0]), "+f"(d[1]), "+f"(d[2]), "+f"(d[3])
                 : "r"(a[0]), "r"(a[1]), "r"(a[2]), "r"(a[3]), "r"(b[0]), "r"(b[1]));
}
__device__ __forceinline__ float ex2a(float x) {
    float r;
    asm("ex2.approx.f32 %0, %1;" : "=f"(r) : "f"(x));
    return r;
}
// pack (x,y) -> bf16x2 hi part and residual lo part
__device__ __forceinline__ void pack_split(float x, float y, uint32_t& hi, uint32_t& lo) {
    uint32_t h;
    asm("cvt.rn.bf16x2.f32 %0, %1, %2;" : "=r"(h) : "f"(y), "f"(x));
    float hx = __uint_as_float(h << 16);
    float hy = __uint_as_float(h & 0xFFFF0000u);
    uint32_t l;
    float lx = x - hx, ly = y - hy;
    asm("cvt.rn.bf16x2.f32 %0, %1, %2;" : "=r"(l) : "f"(ly), "f"(lx));
    hi = h; lo = l;
}
#define CP_ASYNC16(dst, src) \
    asm volatile("cp.async.ca.shared.global [%0], [%1], 16;" :: "r"(dst), "l"(src))
#define CP_COMMIT() asm volatile("cp.async.commit_group;" ::: "memory")
#define CP_WAIT1() asm volatile("cp.async.wait_group 1;" ::: "memory")
#define CP_WAIT0() asm volatile("cp.async.wait_group 0;" ::: "memory")

// ============= split-bf16 tensor-core GEMM: C = A[M,K] @ W[N,K]^T + bias =====
// mode 0: write fp32 C.  mode 1: write pre-split bf16 hi/lo (for Q/K/V).
#define BM 128
#define BN 128
#define BK 32
#define STR 40
#define OFF_AHI 0
#define OFF_ALO (BM * STR)
#define OFF_BHI (2 * BM * STR)
#define OFF_BLO (2 * BM * STR + BN * STR)
#define STAGE_ELEMS (2 * BM * STR + 2 * BN * STR)
#define GEMM_SMEM (2 * STAGE_ELEMS * 2)

__device__ __forceinline__ void split_store4(__nv_bfloat16* hp, __nv_bfloat16* lp, float4 v) {
    __nv_bfloat16 h0 = __float2bfloat16(v.x), h1 = __float2bfloat16(v.y);
    __nv_bfloat16 h2 = __float2bfloat16(v.z), h3 = __float2bfloat16(v.w);
    __nv_bfloat16 l0 = __float2bfloat16(v.x - __bfloat162float(h0));
    __nv_bfloat16 l1 = __float2bfloat16(v.y - __bfloat162float(h1));
    __nv_bfloat16 l2 = __float2bfloat16(v.z - __bfloat162float(h2));
    __nv_bfloat16 l3 = __float2bfloat16(v.w - __bfloat162float(h3));
    __nv_bfloat162 p;
    p.x = h0; p.y = h1; *(__nv_bfloat162*)(hp)     = p;
    p.x = h2; p.y = h3; *(__nv_bfloat162*)(hp + 2) = p;
    p.x = l0; p.y = l1; *(__nv_bfloat162*)(lp)     = p;
    p.x = l2; p.y = l3; *(__nv_bfloat162*)(lp + 2) = p;
}

__global__ __launch_bounds__(256)
void mma_gemm_split(const float* __restrict__ A, const float* __restrict__ W,
                    const float* __restrict__ bias, float* __restrict__ C,
                    __nv_bfloat16* __restrict__ Chi, __nv_bfloat16* __restrict__ Clo,
                    int mode, int M, int N, int K)
{
    extern __shared__ __align__(16) __nv_bfloat16 sm[];
    const int tid = threadIdx.x;
    const int lane = tid & 31, wid = tid >> 5;
    const int wm = wid & 3;
    const int wn = wid >> 2;
    const int bx = blockIdx.x, by = blockIdx.y;

    const float* Ab = A + (size_t)(by * BM) * K;
    const float* Wb = W + (size_t)(bx * BN) * K;

    float acc[2][8][4];
    #pragma unroll
    for (int i = 0; i < 2; ++i)
        #pragma unroll
        for (int j = 0; j < 8; ++j)
            #pragma unroll
            for (int t = 0; t < 4; ++t) acc[i][j][t] = 0.f;

    float4 ra[4], rb[4];
    const uint32_t sbase = smem_u32(sm);
    const uint32_t aoff = (uint32_t)((wm * 32 + (lane & 15)) * STR) * 2 + (lane >> 4) * 16;
    const uint32_t boff = (uint32_t)((wn * 64 + (lane & 7) + ((lane >> 4) << 3)) * STR) * 2
                        + ((lane >> 3) & 1) * 16;
    const int nit = K / BK;

    {
        #pragma unroll
        for (int l = 0; l < 4; ++l) {
            int slot = tid + l * 256;
            int r = slot >> 3, q = slot & 7;
            ra[l] = *(const float4*)(Ab + (size_t)r * K + q * 4);
            rb[l] = *(const float4*)(Wb + (size_t)r * K + q * 4);
        }
        #pragma unroll
        for (int l = 0; l < 4; ++l) {
            int slot = tid + l * 256;
            int r = slot >> 3, q = slot & 7;
            int off = r * STR + q * 4;
            split_store4(sm + OFF_AHI + off, sm + OFF_ALO + off, ra[l]);
            split_store4(sm + OFF_BHI + off, sm + OFF_BLO + off, rb[l]);
        }
        __syncthreads();
    }

    for (int i = 0; i < nit; ++i) {
        if (i + 1 < nit) {
            const int k0 = (i + 1) * BK;
            #pragma unroll
            for (int l = 0; l < 4; ++l) {
                int slot = tid + l * 256;
                int r = slot >> 3, q = slot & 7;
                ra[l] = *(const float4*)(Ab + (size_t)r * K + k0 + q * 4);
                rb[l] = *(const float4*)(Wb + (size_t)r * K + k0 + q * 4);
            }
        }
        {
            const uint32_t sa = sbase + (uint32_t)((i & 1) * STAGE_ELEMS) * 2;
            #pragma unroll
            for (int ks = 0; ks < 2; ++ks) {
                const uint32_t kb = ks * 32;
                uint32_t ah[2][4], al[2][4], bh[4][4], bl[4][4];
                #pragma unroll
                for (int mf = 0; mf < 2; ++mf) {
                    ldm_x4(ah[mf], sa + OFF_AHI * 2 + aoff + mf * (16 * STR * 2) + kb);
                    ldm_x4(al[mf], sa + OFF_ALO * 2 + aoff + mf * (16 * STR * 2) + kb);
                }
                #pragma unroll
                for (int nb = 0; nb < 4; ++nb) {
                    ldm_x4(bh[nb], sa + OFF_BHI * 2 + boff + nb * (16 * STR * 2) + kb);
                    ldm_x4(bl[nb], sa + OFF_BLO * 2 + boff + nb * (16 * STR * 2) + kb);
                }
                #pragma unroll
                for (int mf = 0; mf < 2; ++mf)
                    #pragma unroll
                    for (int nf = 0; nf < 8; ++nf) {
                        const uint32_t* bhp = &bh[nf >> 1][(nf & 1) * 2];
                        const uint32_t* blp = &bl[nf >> 1][(nf & 1) * 2];
                        mma16816(acc[mf][nf], ah[mf], bhp);
                        mma16816(acc[mf][nf], ah[mf], blp);
                        mma16816(acc[mf][nf], al[mf], bhp);
                    }
            }
        }
        if (i + 1 < nit) {
            __nv_bfloat16* base = sm + ((i + 1) & 1) * STAGE_ELEMS;
            #pragma unroll
            for (int l = 0; l < 4; ++l) {
                int slot = tid + l * 256;
                int r = slot >> 3, q = slot & 7;
                int off = r * STR + q * 4;
                split_store4(base + OFF_AHI + off, base + OFF_ALO + off, ra[l]);
                split_store4(base + OFF_BHI + off, base + OFF_BLO + off, rb[l]);
            }
        }
        __syncthreads();
    }

    const int row0 = by * BM + wm * 32 + (lane >> 2);
    const int col0 = bx * BN + wn * 64 + 2 * (lane & 3);
    #pragma unroll
    for (int mf = 0; mf < 2; ++mf) {
        #pragma unroll
        for (int nf = 0; nf < 8; ++nf) {
            const int r0 = row0 + mf * 16;
            const int c = col0 + nf * 8;
            const float b0 = bias[c], b1 = bias[c + 1];
            float f00 = acc[mf][nf][0] + b0, f01 = acc[mf][nf][1] + b1;
            float f10 = acc[mf][nf][2] + b0, f11 = acc[mf][nf][3] + b1;
            if (mode == 0) {
                *(float2*)(C + (size_t)r0 * N + c) = make_float2(f00, f01);
                *(float2*)(C + (size_t)(r0 + 8) * N + c) = make_float2(f10, f11);
            } else {
                __nv_bfloat162 h, l;
                h.x = __float2bfloat16(f00); h.y = __float2bfloat16(f01);
                l.x = __float2bfloat16(f00 - __bfloat162float(h.x));
                l.y = __float2bfloat16(f01 - __bfloat162float(h.y));
                *(__nv_bfloat162*)(Chi + (size_t)r0 * N + c) = h;
                *(__nv_bfloat162*)(Clo + (size_t)r0 * N + c) = l;
                h.x = __float2bfloat16(f10); h.y = __float2bfloat16(f11);
                l.x = __float2bfloat16(f10 - __bfloat162float(h.x));
                l.y = __float2bfloat16(f11 - __bfloat162float(h.y));
                *(__nv_bfloat162*)(Chi + (size_t)(r0 + 8) * N + c) = h;
                *(__nv_bfloat162*)(Clo + (size_t)(r0 + 8) * N + c) = l;
            }
        }
    }
}

// =================== tensor-core flash attention ==============================
// Block: 128 threads (4 warps), 128 q rows; K tiles of 64 keys, cp.async 2-stage.
#define ASTR 72
#define A_QLO (128 * ASTR)          // 9216 elems
#define A_KV  (2 * 128 * ASTR)      // 18432 elems
#define A_BUF (4 * 64 * ASTR)       // 18432 elems per stage (khi,klo,vhi,vlo)
#define A_SUB (64 * ASTR)           // 4608
#define A_SMEM ((A_KV + 2 * A_BUF) * 2)   // 110592 bytes
#define SC_L2E 0.18033688011112042f       // (1/sqrt(64)) * log2(e)

__global__ __launch_bounds__(128)
void gqa_attn_tc(const __nv_bfloat16* __restrict__ qhi, const __nv_bfloat16* __restrict__ qlo,
                 const __nv_bfloat16* __restrict__ khi, const __nv_bfloat16* __restrict__ klo,
                 const __nv_bfloat16* __restrict__ vhi, const __nv_bfloat16* __restrict__ vlo,
                 float* __restrict__ O)
{
    extern __shared__ __align__(16) __nv_bfloat16 smb[];
    const int tid = threadIdx.x;
    const int lane = tid & 31, warp = tid >> 5;
    const int bh = blockIdx.x, qt = blockIdx.y;
    const int b = bh / NH, h = bh % NH;
    const int kvh = h >> 2;                 // NH/NKV = 4

    const uint32_t sb = smem_u32(smb);
    const __nv_bfloat16* qh = qhi + (size_t)(b * SEQ + qt * 128) * HIDDEN + h * HD;
    const __nv_bfloat16* ql = qlo + (size_t)(b * SEQ + qt * 128) * HIDDEN + h * HD;
    const __nv_bfloat16* kh = khi + (size_t)(b * SEQ) * KVDIM + kvh * HD;
    const __nv_bfloat16* kl = klo + (size_t)(b * SEQ) * KVDIM + kvh * HD;
    const __nv_bfloat16* vh = vhi + (size_t)(b * SEQ) * KVDIM + kvh * HD;
    const __nv_bfloat16* vl = vlo + (size_t)(b * SEQ) * KVDIM + kvh * HD;

    // ---- load Q tile (hi+lo): 128 rows x 8 chunks x 2 = 2048 16B slots ----
    #pragma unroll
    for (int l = 0; l < 16; ++l) {
        int idx = tid + l * 128;
        int sel = idx >> 10, rem = idx & 1023, r = rem >> 3, c = rem & 7;
        const __nv_bfloat16* src = (sel ? ql : qh) + (size_t)r * HIDDEN + c * 8;
        *(uint4*)(smb + sel * A_QLO + r * ASTR + c * 8) = *(const uint4*)src;
    }

    // ---- cp.async staging of K/V tiles ----
    auto stage = [&](int t, int s) {
        #pragma unroll
        for (int l = 0; l < 16; ++l) {
            int idx = tid + l * 128;
            int sel = idx >> 9, rem = idx & 511, r = rem >> 3, c = rem & 7;
            const __nv_bfloat16* src =
                (sel == 0 ? kh : sel == 1 ? kl : sel == 2 ? vh : vl)
                + (size_t)(t * 64 + r) * KVDIM + c * 8;
            uint32_t dst = sb + (uint32_t)(A_KV + s * A_BUF + sel * A_SUB + r * ASTR + c * 8) * 2;
            CP_ASYNC16(dst, src);
        }
    };

    float m_[2][2], l_[2][2], o[2][8][4];
    #pragma unroll
    for (int mf = 0; mf < 2; ++mf) {
        m_[mf][0] = m_[mf][1] = -1e30f;
        l_[mf][0] = l_[mf][1] = 0.f;
        #pragma unroll
        for (int nf = 0; nf < 8; ++nf)
            #pragma unroll
            for (int t = 0; t < 4; ++t) o[mf][nf][t] = 0.f;
    }

    stage(0, 0);
    CP_COMMIT();

    for (int t = 0; t < SEQ / 64; ++t) {
        const int s = t & 1;
        if (t + 1 < SEQ / 64) { stage(t + 1, s ^ 1); CP_COMMIT(); CP_WAIT1(); }
        else CP_WAIT0();
        __syncthreads();

        const uint32_t kb = sb + (uint32_t)(A_KV + s * A_BUF) * 2;

        // ---- scores S = Q K^T (split, fp32 accum) ----
        float sacc[2][8][4];
        #pragma unroll
        for (int mf = 0; mf < 2; ++mf)
            #pragma unroll
            for (int nf = 0; nf < 8; ++nf)
                #pragma unroll
                for (int x = 0; x < 4; ++x) sacc[mf][nf][x] = 0.f;

        #pragma unroll
        for (int ks = 0; ks < 4; ++ks) {
            uint32_t ah[2][4], al[2][4];
            #pragma unroll
            for (int mf = 0; mf < 2; ++mf) {
                uint32_t qa = sb + (uint32_t)((warp * 32 + mf * 16 + (lane & 15)) * ASTR) * 2
                            + (lane >> 4) * 16 + ks * 32;
                ldm_x4(ah[mf], qa);
                ldm_x4(al[mf], qa + A_QLO * 2);
            }
            #pragma unroll
            for (int nb = 0; nb < 4; ++nb) {
                uint32_t bh4[4], bl4[4];
                uint32_t ka = kb + (uint32_t)((nb * 16 + (lane & 7) + ((lane >> 4) << 3)) * ASTR) * 2
                            + ((lane >> 3) & 1) * 16 + ks * 32;
                ldm_x4(bh4, ka);
                ldm_x4(bl4, ka + A_SUB * 2);
                #pragma unroll
                for (int mf = 0; mf < 2; ++mf)
                    #pragma unroll
                    for (int hf = 0; hf < 2; ++hf) {
                        float* d = sacc[mf][nb * 2 + hf];
                        mma16816(d, ah[mf], bh4 + hf * 2);
                        mma16816(d, ah[mf], bl4 + hf * 2);
                        mma16816(d, al[mf], bh4 + hf * 2);
                    }
            }
        }

        // ---- online softmax (registers + quad shuffles) ----
        #pragma unroll
        for (int mf = 0; mf < 2; ++mf) {
            float r0 = -1e30f, r1 = -1e30f;
            #pragma unroll
            for (int nf = 0; nf < 8; ++nf) {
                r0 = fmaxf(r0, fmaxf(sacc[mf][nf][0], sacc[mf][nf][1]));
                r1 = fmaxf(r1, fmaxf(sacc[mf][nf][2], sacc[mf][nf][3]));
            }
            r0 = fmaxf(r0, __shfl_xor_sync(0xFFFFFFFFu, r0, 1));
            r0 = fmaxf(r0, __shfl_xor_sync(0xFFFFFFFFu, r0, 2));
            r1 = fmaxf(r1, __shfl_xor_sync(0xFFFFFFFFu, r1, 1));
            r1 = fmaxf(r1, __shfl_xor_sync(0xFFFFFFFFu, r1, 2));
            const float mn0 = fmaxf(m_[mf][0], r0);
            const float mn1 = fmaxf(m_[mf][1], r1);
            const float c0 = ex2a((m_[mf][0] - mn0) * SC_L2E);
            const float c1 = ex2a((m_[mf][1] - mn1) * SC_L2E);
            m_[mf][0] = mn0; m_[mf][1] = mn1;
            float rs0 = 0.f, rs1 = 0.f;
            #pragma unroll
            for (int nf = 0; nf < 8; ++nf) {
                float* sp = sacc[mf][nf];
                sp[0] = ex2a((sp[0] - mn0) * SC_L2E);
                sp[1] = ex2a((sp[1] - mn0) * SC_L2E);
                sp[2] = ex2a((sp[2] - mn1) * SC_L2E);
                sp[3] = ex2a((sp[3] - mn1) * SC_L2E);
                rs0 += sp[0] + sp[1];
                rs1 += sp[2] + sp[3];
                o[mf][nf][0] *= c0; o[mf][nf][1] *= c0;
                o[mf][nf][2] *= c1; o[mf][nf][3] *= c1;
            }
            rs0 += __shfl_xor_sync(0xFFFFFFFFu, rs0, 1);
            rs0 += __shfl_xor_sync(0xFFFFFFFFu, rs0, 2);
            rs1 += __shfl_xor_sync(0xFFFFFFFFu, rs1, 1);
            rs1 += __shfl_xor_sync(0xFFFFFFFFu, rs1, 2);
            l_[mf][0] = l_[mf][0] * c0 + rs0;
            l_[mf][1] = l_[mf][1] * c1 + rs1;
        }

        // ---- O += P V (P split in-register, V split from smem) ----
        #pragma unroll
        for (int ks2 = 0; ks2 < 4; ++ks2) {
            uint32_t pah[2][4], pal[2][4];
            #pragma unroll
            for (int mf = 0; mf < 2; ++mf) {
                float* s0 = sacc[mf][2 * ks2];
                float* s1 = sacc[mf][2 * ks2 + 1];
                pack_split(s0[0], s0[1], pah[mf][0], pal[mf][0]);
                pack_split(s0[2], s0[3], pah[mf][1], pal[mf][1]);
                pack_split(s1[0], s1[1], pah[mf][2], pal[mf][2]);
                pack_split(s1[2], s1[3], pah[mf][3], pal[mf][3]);
            }
            #pragma unroll
            for (int nblk = 0; nblk < 4; ++nblk) {
                uint32_t vh4[4], vl4[4];
                uint32_t va = kb + (uint32_t)(2 * A_SUB) * 2
                            + (uint32_t)((ks2 * 16 + (lane & 7) + ((lane >> 3) & 1) * 8) * ASTR
                                         + nblk * 16 + (lane >> 4) * 8) * 2;
                ldm_x4_t(vh4, va);
                ldm_x4_t(vl4, va + A_SUB * 2);
                #pragma unroll
                for (int mf = 0; mf < 2; ++mf)
                    #pragma unroll
                    for (int hf = 0; hf < 2; ++hf) {
                        float* d = o[mf][nblk * 2 + hf];
                        mma16816(d, pah[mf], vh4 + hf * 2);
                        mma16816(d, pah[mf], vl4 + hf * 2);
                        mma16816(d, pal[mf], vh4 + hf * 2);
                    }
            }
        }
        __syncthreads();
    }

    // ---- epilogue ----
    #pragma unroll
    for (int mf = 0; mf < 2; ++mf) {
        const float i0 = 1.f / l_[mf][0];
        const float i1 = 1.f / l_[mf][1];
        const int row = b * SEQ + qt * 128 + warp * 32 + mf * 16 + (lane >> 2);
        #pragma unroll
        for (int nf = 0; nf < 8; ++nf) {
            const int col = h * HD + nf * 8 + (lane & 3) * 2;
            *(float2*)(O + (size_t)row * HIDDEN + col) =
                make_float2(o[mf][nf][0] * i0, o[mf][nf][1] * i0);
            *(float2*)(O + (size_t)(row + 8) * HIDDEN + col) =
                make_float2(o[mf][nf][2] * i1, o[mf][nf][3] * i1);
        }
    }
}

// ---------------- launch ------------------------------------------------------
extern "C" void kernel_launch(void* const* d_in, const int* in_sizes, int n_in,
                              void* d_out, int out_size)
{
    const float* x  = (const float*)d_in[0];
    const float* wq = (const float*)d_in[1];
    const float* bq = (const float*)d_in[2];
    const float* wk = (const float*)d_in[3];
    const float* bk = (const float*)d_in[4];
    const float* wv = (const float*)d_in[5];
    const float* bv = (const float*)d_in[6];
    const float* wo = (const float*)d_in[7];
    const float* bo = (const float*)d_in[8];
    float* out = (float*)d_out;

    __nv_bfloat16 *qhi, *qlo, *khi, *klo, *vhi, *vlo;
    float* attn;
    cudaGetSymbolAddress((void**)&qhi, g_qhi);
    cudaGetSymbolAddress((void**)&qlo, g_qlo);
    cudaGetSymbolAddress((void**)&khi, g_khi);
    cudaGetSymbolAddress((void**)&klo, g_klo);
    cudaGetSymbolAddress((void**)&vhi, g_vhi);
    cudaGetSymbolAddress((void**)&vlo, g_vlo);
    cudaGetSymbolAddress((void**)&attn, g_attn);

    cudaFuncSetAttribute(mma_gemm_split,
                         cudaFuncAttributeMaxDynamicSharedMemorySize, GEMM_SMEM);
    cudaFuncSetAttribute(gqa_attn_tc,
                         cudaFuncAttributeMaxDynamicSharedMemorySize, A_SMEM);

    // Q/K/V projections -> pre-split bf16 hi/lo
    mma_gemm_split<<<dim3(HIDDEN / BN, MTOT / BM), 256, GEMM_SMEM>>>(
        x, wq, bq, nullptr, qhi, qlo, 1, MTOT, HIDDEN, HIDDEN);
    mma_gemm_split<<<dim3(KVDIM / BN, MTOT / BM), 256, GEMM_SMEM>>>(
        x, wk, bk, nullptr, khi, klo, 1, MTOT, KVDIM, HIDDEN);
    mma_gemm_split<<<dim3(KVDIM / BN, MTOT / BM), 256, GEMM_SMEM>>>(
        x, wv, bv, nullptr, vhi, vlo, 1, MTOT, KVDIM, HIDDEN);

    // tensor-core flash attention
    gqa_attn_tc<<<dim3(BATCH * NH, SEQ / 128), 128, A_SMEM>>>(
        qhi, qlo, khi, klo, vhi, vlo, attn);

    // output projection (fp32 out)
    mma_gemm_split<<<dim3(HIDDEN / BN, MTOT / BM), 256, GEMM_SMEM>>>(
        attn, wo, bo, out, nullptr, nullptr, 0, MTOT, HIDDEN, HIDDEN);
}